// round 4
// baseline (speedup 1.0000x reference)
#include <cuda_runtime.h>

// Fused stream-mix kernel:
//   out[bs, i, d] = (sum_j h_res[bs, i, j] * x[bs, j, d]) * h_out[bs, d]
//                   + h_post[bs, i] * x[bs, i, d]
// x [BS, 4, 1024], h_res [BS, 4, 4], h_out [BS, 1024], h_post [BS, 4],
// out [BS, 4, 1024].  HBM-bound streaming (~578 MB single-touch).
//
// R4: grid-stride persistent blocks with one-iteration prefetch of the 5
// wide loads — the load queue never drains across token boundaries
// (steady-state 10 outstanding LDG.128 per thread during compute+store).

constexpr int N_STREAMS = 4;
constexpr int D_MODEL   = 1024;
constexpr int D4        = D_MODEL / 4;   // 256 float4 columns
constexpr int GRID      = 2048;          // blocks; each handles BS/GRID tokens

__global__ __launch_bounds__(D4)
void fused_stream_mix_kernel(const float* __restrict__ x,
                             const float* __restrict__ h_res,
                             const float* __restrict__ h_out,
                             const float* __restrict__ h_post,
                             float* __restrict__ out,
                             int BS) {
    const int t = threadIdx.x;               // float4 column in [0, 256)
    const int stride = gridDim.x;
    long long bs = blockIdx.x;
    if (bs >= BS) return;

    // Prologue: issue current token's 5 wide loads.
    const float4* xp  = reinterpret_cast<const float4*>(x) + bs * (N_STREAMS * (long long)D4);
    const float4* hop = reinterpret_cast<const float4*>(h_out) + bs * (long long)D4;
    float4 x0 = xp[0 * D4 + t];
    float4 x1 = xp[1 * D4 + t];
    float4 x2 = xp[2 * D4 + t];
    float4 x3 = xp[3 * D4 + t];
    float4 ho = hop[t];

    for (;;) {
        // Prefetch next token's bulk loads before touching current data.
        const long long nbs = bs + stride;
        const bool has_next = (nbs < BS);
        float4 nx0, nx1, nx2, nx3, nho;
        if (has_next) {
            const float4* nxp  = reinterpret_cast<const float4*>(x) + nbs * (N_STREAMS * (long long)D4);
            const float4* nhop = reinterpret_cast<const float4*>(h_out) + nbs * (long long)D4;
            nx0 = nxp[0 * D4 + t];
            nx1 = nxp[1 * D4 + t];
            nx2 = nxp[2 * D4 + t];
            nx3 = nxp[3 * D4 + t];
            nho = nhop[t];
        }

        // Broadcast scalar loads for the current token (warp-uniform address).
        const float* hr = h_res + bs * (N_STREAMS * N_STREAMS);
        const float* hp = h_post + bs * N_STREAMS;
        const float r00 = hr[0],  r01 = hr[1],  r02 = hr[2],  r03 = hr[3];
        const float r10 = hr[4],  r11 = hr[5],  r12 = hr[6],  r13 = hr[7];
        const float r20 = hr[8],  r21 = hr[9],  r22 = hr[10], r23 = hr[11];
        const float r30 = hr[12], r31 = hr[13], r32 = hr[14], r33 = hr[15];
        const float p0 = hp[0], p1 = hp[1], p2 = hp[2], p3 = hp[3];

        float4 o0, o1, o2, o3;

        o0.x = fmaf(r00, x0.x, fmaf(r01, x1.x, fmaf(r02, x2.x, r03 * x3.x))) * ho.x + p0 * x0.x;
        o0.y = fmaf(r00, x0.y, fmaf(r01, x1.y, fmaf(r02, x2.y, r03 * x3.y))) * ho.y + p0 * x0.y;
        o0.z = fmaf(r00, x0.z, fmaf(r01, x1.z, fmaf(r02, x2.z, r03 * x3.z))) * ho.z + p0 * x0.z;
        o0.w = fmaf(r00, x0.w, fmaf(r01, x1.w, fmaf(r02, x2.w, r03 * x3.w))) * ho.w + p0 * x0.w;

        o1.x = fmaf(r10, x0.x, fmaf(r11, x1.x, fmaf(r12, x2.x, r13 * x3.x))) * ho.x + p1 * x1.x;
        o1.y = fmaf(r10, x0.y, fmaf(r11, x1.y, fmaf(r12, x2.y, r13 * x3.y))) * ho.y + p1 * x1.y;
        o1.z = fmaf(r10, x0.z, fmaf(r11, x1.z, fmaf(r12, x2.z, r13 * x3.z))) * ho.z + p1 * x1.z;
        o1.w = fmaf(r10, x0.w, fmaf(r11, x1.w, fmaf(r12, x2.w, r13 * x3.w))) * ho.w + p1 * x1.w;

        o2.x = fmaf(r20, x0.x, fmaf(r21, x1.x, fmaf(r22, x2.x, r23 * x3.x))) * ho.x + p2 * x2.x;
        o2.y = fmaf(r20, x0.y, fmaf(r21, x1.y, fmaf(r22, x2.y, r23 * x3.y))) * ho.y + p2 * x2.y;
        o2.z = fmaf(r20, x0.z, fmaf(r21, x1.z, fmaf(r22, x2.z, r23 * x3.z))) * ho.z + p2 * x2.z;
        o2.w = fmaf(r20, x0.w, fmaf(r21, x1.w, fmaf(r22, x2.w, r23 * x3.w))) * ho.w + p2 * x2.w;

        o3.x = fmaf(r30, x0.x, fmaf(r31, x1.x, fmaf(r32, x2.x, r33 * x3.x))) * ho.x + p3 * x3.x;
        o3.y = fmaf(r30, x0.y, fmaf(r31, x1.y, fmaf(r32, x2.y, r33 * x3.y))) * ho.y + p3 * x3.y;
        o3.z = fmaf(r30, x0.z, fmaf(r31, x1.z, fmaf(r32, x2.z, r33 * x3.z))) * ho.z + p3 * x3.z;
        o3.w = fmaf(r30, x0.w, fmaf(r31, x1.w, fmaf(r32, x2.w, r33 * x3.w))) * ho.w + p3 * x3.w;

        float4* op = reinterpret_cast<float4*>(out) + bs * (N_STREAMS * (long long)D4);
        op[0 * D4 + t] = o0;
        op[1 * D4 + t] = o1;
        op[2 * D4 + t] = o2;
        op[3 * D4 + t] = o3;

        if (!has_next) break;
        bs = nbs;
        x0 = nx0; x1 = nx1; x2 = nx2; x3 = nx3; ho = nho;
    }
}

extern "C" void kernel_launch(void* const* d_in, const int* in_sizes, int n_in,
                              void* d_out, int out_size) {
    const float* x      = (const float*)d_in[0];  // [B,S,N,D]
    const float* h_res  = (const float*)d_in[1];  // [B,S,N,N]
    const float* h_out  = (const float*)d_in[2];  // [B,S,D]
    const float* h_post = (const float*)d_in[3];  // [B,S,N]
    float* out = (float*)d_out;

    const int BS = in_sizes[1] / (N_STREAMS * N_STREAMS);
    const int grid = BS < GRID ? BS : GRID;

    fused_stream_mix_kernel<<<grid, D4>>>(x, h_res, h_out, h_post, out, BS);
}

// round 6
// speedup vs baseline: 1.0549x; 1.0549x over previous
#include <cuda_runtime.h>

// Fused stream-mix kernel:
//   out[bs, i, d] = (sum_j h_res[bs, i, j] * x[bs, j, d]) * h_out[bs, d]
//                   + h_post[bs, i] * x[bs, i, d]
// x [BS, 4, 1024], h_res [BS, 4, 4], h_out [BS, 1024], h_post [BS, 4],
// out [BS, 4, 1024].  HBM-bound streaming (~578 MB single-touch).
//
// R6 (= R5 retry after infra failure): R2 structure (one block per token —
// best measured DRAM%) + occupancy push: __launch_bounds__(256, 6) caps regs
// at 42 (6 CTAs/SM vs 5 at regs=48). Outputs computed and stored row-by-row
// to keep the live-register window narrow so the cap doesn't spill.

constexpr int N_STREAMS = 4;
constexpr int D_MODEL   = 1024;
constexpr int D4        = D_MODEL / 4;   // 256 float4 columns

__global__ __launch_bounds__(D4, 6)
void fused_stream_mix_kernel(const float* __restrict__ x,
                             const float* __restrict__ h_res,
                             const float* __restrict__ h_out,
                             const float* __restrict__ h_post,
                             float* __restrict__ out) {
    const long long bs = blockIdx.x;          // token index in [0, B*S)
    const int t = threadIdx.x;                // float4 column in [0, 256)

    const float4* xp  = reinterpret_cast<const float4*>(x) + bs * (N_STREAMS * (long long)D4);
    const float4* hop = reinterpret_cast<const float4*>(h_out) + bs * (long long)D4;

    // Front-batched wide loads: 5 independent LDG.128 in flight.
    const float4 x0 = xp[0 * D4 + t];
    const float4 x1 = xp[1 * D4 + t];
    const float4 x2 = xp[2 * D4 + t];
    const float4 x3 = xp[3 * D4 + t];
    const float4 ho = hop[t];

    // Broadcast scalar loads (warp-uniform address -> L1 broadcast).
    const float* hr = h_res + bs * (N_STREAMS * N_STREAMS);
    const float* hp = h_post + bs * N_STREAMS;

    float4* op = reinterpret_cast<float4*>(out) + bs * (N_STREAMS * (long long)D4);

    // Compute and store one output stream at a time: narrow live window,
    // stores are issue-only so the write stream drains while we compute.
    {
        const float r0 = hr[0], r1 = hr[1], r2 = hr[2], r3 = hr[3], p = hp[0];
        float4 o;
        o.x = fmaf(r0, x0.x, fmaf(r1, x1.x, fmaf(r2, x2.x, r3 * x3.x))) * ho.x + p * x0.x;
        o.y = fmaf(r0, x0.y, fmaf(r1, x1.y, fmaf(r2, x2.y, r3 * x3.y))) * ho.y + p * x0.y;
        o.z = fmaf(r0, x0.z, fmaf(r1, x1.z, fmaf(r2, x2.z, r3 * x3.z))) * ho.z + p * x0.z;
        o.w = fmaf(r0, x0.w, fmaf(r1, x1.w, fmaf(r2, x2.w, r3 * x3.w))) * ho.w + p * x0.w;
        op[0 * D4 + t] = o;
    }
    {
        const float r0 = hr[4], r1 = hr[5], r2 = hr[6], r3 = hr[7], p = hp[1];
        float4 o;
        o.x = fmaf(r0, x0.x, fmaf(r1, x1.x, fmaf(r2, x2.x, r3 * x3.x))) * ho.x + p * x1.x;
        o.y = fmaf(r0, x0.y, fmaf(r1, x1.y, fmaf(r2, x2.y, r3 * x3.y))) * ho.y + p * x1.y;
        o.z = fmaf(r0, x0.z, fmaf(r1, x1.z, fmaf(r2, x2.z, r3 * x3.z))) * ho.z + p * x1.z;
        o.w = fmaf(r0, x0.w, fmaf(r1, x1.w, fmaf(r2, x2.w, r3 * x3.w))) * ho.w + p * x1.w;
        op[1 * D4 + t] = o;
    }
    {
        const float r0 = hr[8], r1 = hr[9], r2 = hr[10], r3 = hr[11], p = hp[2];
        float4 o;
        o.x = fmaf(r0, x0.x, fmaf(r1, x1.x, fmaf(r2, x2.x, r3 * x3.x))) * ho.x + p * x2.x;
        o.y = fmaf(r0, x0.y, fmaf(r1, x1.y, fmaf(r2, x2.y, r3 * x3.y))) * ho.y + p * x2.y;
        o.z = fmaf(r0, x0.z, fmaf(r1, x1.z, fmaf(r2, x2.z, r3 * x3.z))) * ho.z + p * x2.z;
        o.w = fmaf(r0, x0.w, fmaf(r1, x1.w, fmaf(r2, x2.w, r3 * x3.w))) * ho.w + p * x2.w;
        op[2 * D4 + t] = o;
    }
    {
        const float r0 = hr[12], r1 = hr[13], r2 = hr[14], r3 = hr[15], p = hp[3];
        float4 o;
        o.x = fmaf(r0, x0.x, fmaf(r1, x1.x, fmaf(r2, x2.x, r3 * x3.x))) * ho.x + p * x3.x;
        o.y = fmaf(r0, x0.y, fmaf(r1, x1.y, fmaf(r2, x2.y, r3 * x3.y))) * ho.y + p * x3.y;
        o.z = fmaf(r0, x0.z, fmaf(r1, x1.z, fmaf(r2, x2.z, r3 * x3.z))) * ho.z + p * x3.z;
        o.w = fmaf(r0, x0.w, fmaf(r1, x1.w, fmaf(r2, x2.w, r3 * x3.w))) * ho.w + p * x3.w;
        op[3 * D4 + t] = o;
    }
}

extern "C" void kernel_launch(void* const* d_in, const int* in_sizes, int n_in,
                              void* d_out, int out_size) {
    const float* x      = (const float*)d_in[0];  // [B,S,N,D]
    const float* h_res  = (const float*)d_in[1];  // [B,S,N,N]
    const float* h_out  = (const float*)d_in[2];  // [B,S,D]
    const float* h_post = (const float*)d_in[3];  // [B,S,N]
    float* out = (float*)d_out;

    const int BS = in_sizes[1] / (N_STREAMS * N_STREAMS);

    fused_stream_mix_kernel<<<BS, D4>>>(x, h_res, h_out, h_post, out);
}